// round 10
// baseline (speedup 1.0000x reference)
#include <cuda_runtime.h>
#include <math.h>

// Problem constants
#define BB   32
#define SS   1024
#define HH   2
#define EE   4
#define FF   16
#define VV   8
#define NT   (BB * SS)      // 32768 tokens
#define BHN  (BB * HH)      // 64 (b,h) pairs
#define NSPLIT 8
#define KCH  (SS / NSPLIT)  // 128 keys per block

typedef unsigned long long u64;

// Scratch (no runtime allocation allowed)
__device__ float4 g_x[NT];                 // residual stream [token][E]
__device__ float2 g_q[BHN * SS];           // per-(b,h) q, pre-scaled
__device__ float2 g_k[BHN * SS];
__device__ float2 g_v[BHN * SS];
__device__ float4 g_part[BHN * SS * NSPLIT]; // (m, sum, ax, ay) partials

// ---------------------------------------------------------------------------
// f32x2 packed-math helpers (sm_103a)
// ---------------------------------------------------------------------------
__device__ __forceinline__ u64 pack2(float lo, float hi) {
    u64 r;
    asm("mov.b64 %0, {%1, %2};" : "=l"(r)
        : "r"(__float_as_uint(lo)), "r"(__float_as_uint(hi)));
    return r;
}
__device__ __forceinline__ void unpack2(u64 v, float& lo, float& hi) {
    unsigned a, b;
    asm("mov.b64 {%0, %1}, %2;" : "=r"(a), "=r"(b) : "l"(v));
    lo = __uint_as_float(a);
    hi = __uint_as_float(b);
}
#define FMA2(d, a, b, c) \
    asm("fma.rn.f32x2 %0, %1, %2, %3;" : "=l"(d) : "l"(a), "l"(b), "l"(c))
#define ADD2(d, a, b) \
    asm("add.rn.f32x2 %0, %1, %2;" : "=l"(d) : "l"(a), "l"(b))

__device__ __forceinline__ float ex2f(float x) {
    float r;
    asm("ex2.approx.f32 %0, %1;" : "=f"(r) : "f"(x));
    return r;
}

// ---------------------------------------------------------------------------
// scalar helpers
// ---------------------------------------------------------------------------
__device__ __forceinline__ void layernorm4(float4 x, const float* __restrict__ g,
                                           const float* __restrict__ b, float* h) {
    float mu = 0.25f * (x.x + x.y + x.z + x.w);
    float d0 = x.x - mu, d1 = x.y - mu, d2 = x.z - mu, d3 = x.w - mu;
    float var = 0.25f * (d0 * d0 + d1 * d1 + d2 * d2 + d3 * d3);
    float r = rsqrtf(var + 1e-5f);
    h[0] = d0 * r * __ldg(g + 0) + __ldg(b + 0);
    h[1] = d1 * r * __ldg(g + 1) + __ldg(b + 1);
    h[2] = d2 * r * __ldg(g + 2) + __ldg(b + 2);
    h[3] = d3 * r * __ldg(g + 3) + __ldg(b + 3);
}

// qkv projection for one token, write q/k/v in (b,h,s,d) float2 layout
__device__ __forceinline__ void qkv_project(int t, const float* h,
                                            const float* __restrict__ wqkv_l) {
    float acc[12];
#pragma unroll
    for (int f = 0; f < 12; f++) {
        const float* w = wqkv_l + f * EE;
        acc[f] = h[0] * __ldg(w) + h[1] * __ldg(w + 1) +
                 h[2] * __ldg(w + 2) + h[3] * __ldg(w + 3);
    }
    int b = t >> 10;            // t / S
    int s = t & (SS - 1);
    // fold 1/sqrt(D) * log2(e) into q so attn does exp2 with no extra mul
    const float qs = 0.70710678118654752f * 1.4426950408889634f;
    g_q[(b * HH + 0) * SS + s] = make_float2(acc[0] * qs, acc[1] * qs);
    g_q[(b * HH + 1) * SS + s] = make_float2(acc[2] * qs, acc[3] * qs);
    g_k[(b * HH + 0) * SS + s] = make_float2(acc[4], acc[5]);
    g_k[(b * HH + 1) * SS + s] = make_float2(acc[6], acc[7]);
    g_v[(b * HH + 0) * SS + s] = make_float2(acc[8], acc[9]);
    g_v[(b * HH + 1) * SS + s] = make_float2(acc[10], acc[11]);
}

__device__ __forceinline__ float gelu_exact(float x) {
    return 0.5f * x * (1.0f + erff(x * 0.70710678118654752f));
}

// ---------------------------------------------------------------------------
// Kernel 1: embedding + LN1 + QKV (layer 0)
// ---------------------------------------------------------------------------
__global__ void embed_qkv_kernel(const int* __restrict__ token_ids,
                                 const float* __restrict__ emb,
                                 const float* __restrict__ ln1_g,
                                 const float* __restrict__ ln1_b,
                                 const float* __restrict__ wqkv) {
    int t = blockIdx.x * blockDim.x + threadIdx.x;
    if (t >= NT) return;
    int tok = __ldg(token_ids + t);
    const float* e = emb + tok * EE;
    float4 x = make_float4(__ldg(e), __ldg(e + 1), __ldg(e + 2), __ldg(e + 3));
    g_x[t] = x;
    float h[EE];
    layernorm4(x, ln1_g, ln1_b, h);
    qkv_project(t, h, wqkv);
}

// ---------------------------------------------------------------------------
// Kernel 2: attention partials, split-K over NSPLIT=8 chunks.
// 4 queries/thread (packed pairs AB, CD). Per key-iter: 2 LDS.128 (batched
// KBATCH=2 up-front for MLP), 4 FMA2 args, 4 EX2 (MUFU 32 cyc = binding
// pipe), 2 ADD2 + 4 FMA2 accum. Per-exp issue cost ~4.5 slots.
// Shift by per-(thread,chunk) upper bound m = |q|*max|k| (softmax is
// shift-invariant; partials carry m for the rescale combine).
// grid = 64 bh * 2 qchunks * 8 ksplits = 1024 blocks, 128 threads
// => ~7 blocks/SM = 28 warps/SM.
// ---------------------------------------------------------------------------
#define KBATCH 2
__global__ void __launch_bounds__(128, 7) attn_kernel() {
    __shared__ ulonglong2 sK[KCH];   // {kx,kx},{ky,ky}
    __shared__ ulonglong2 sV[KCH];   // {vx,vx},{vy,vy}
    __shared__ unsigned sMaxBits;    // max |k|^2 over this chunk (ordered bits)

    int bx = blockIdx.x;
    int bh    = bx >> 4;
    int qc    = (bx >> 3) & 1;
    int kc    = bx & 7;
    int qbase = qc * 512;
    int kbase = kc * KCH;

    if (threadIdx.x == 0) sMaxBits = 0u;
    __syncthreads();

    const float2* __restrict__ Kg = g_k + bh * SS + kbase;
    const float2* __restrict__ Vg = g_v + bh * SS + kbase;
    {
        int i = threadIdx.x;            // KCH == blockDim.x == 128
        float2 kk = Kg[i];
        float2 vv = Vg[i];
        sK[i] = make_ulonglong2(pack2(kk.x, kk.x), pack2(kk.y, kk.y));
        sV[i] = make_ulonglong2(pack2(vv.x, vv.x), pack2(vv.y, vv.y));
        float n2 = fmaf(kk.x, kk.x, kk.y * kk.y);
        atomicMax(&sMaxBits, __float_as_uint(n2));
    }
    __syncthreads();
    float maxKn = sqrtf(__uint_as_float(sMaxBits));

    int qi0 = qbase + threadIdx.x;        // A
    int qi1 = qi0 + 128;                  // B
    int qi2 = qi0 + 256;                  // C
    int qi3 = qi0 + 384;                  // D
    const float2* __restrict__ Qg = g_q + bh * SS;
    float2 qa = Qg[qi0], qb = Qg[qi1], qcv = Qg[qi2], qd = Qg[qi3];

    float mA = sqrtf(fmaf(qa.x, qa.x, qa.y * qa.y)) * maxKn;
    float mB = sqrtf(fmaf(qb.x, qb.x, qb.y * qb.y)) * maxKn;
    float mC = sqrtf(fmaf(qcv.x, qcv.x, qcv.y * qcv.y)) * maxKn;
    float mD = sqrtf(fmaf(qd.x, qd.x, qd.y * qd.y)) * maxKn;

    u64 mAB  = pack2(-mA, -mB),   mCD  = pack2(-mC, -mD);
    u64 qxAB = pack2(qa.x, qb.x), qxCD = pack2(qcv.x, qd.x);
    u64 qyAB = pack2(qa.y, qb.y), qyCD = pack2(qcv.y, qd.y);

    u64 z = pack2(0.f, 0.f);
    u64 sumAB = z, accXAB = z, accYAB = z;
    u64 sumCD = z, accXCD = z, accYCD = z;

#pragma unroll 4
    for (int j0 = 0; j0 < KCH; j0 += KBATCH) {
        ulonglong2 kk[KBATCH], vv[KBATCH];
#pragma unroll
        for (int u = 0; u < KBATCH; u++) {
            kk[u] = sK[j0 + u];
            vv[u] = sV[j0 + u];
        }
#pragma unroll
        for (int u = 0; u < KBATCH; u++) {
            u64 argAB, argCD;
            FMA2(argAB, qyAB, kk[u].y, mAB);
            FMA2(argAB, qxAB, kk[u].x, argAB);
            FMA2(argCD, qyCD, kk[u].y, mCD);
            FMA2(argCD, qxCD, kk[u].x, argCD);
            float a0, a1, c0, c1;
            unpack2(argAB, a0, a1);
            unpack2(argCD, c0, c1);
            float pa = ex2f(a0);
            float pb = ex2f(a1);
            float pc = ex2f(c0);
            float pd = ex2f(c1);
            u64 pAB = pack2(pa, pb);
            u64 pCD = pack2(pc, pd);
            ADD2(sumAB, sumAB, pAB);
            FMA2(accXAB, pAB, vv[u].x, accXAB);
            FMA2(accYAB, pAB, vv[u].y, accYAB);
            ADD2(sumCD, sumCD, pCD);
            FMA2(accXCD, pCD, vv[u].x, accXCD);
            FMA2(accYCD, pCD, vv[u].y, accYCD);
        }
    }

    float sA, sB, sC, sD, axA, axB, axC, axD, ayA, ayB, ayC, ayD;
    unpack2(sumAB, sA, sB);    unpack2(sumCD, sC, sD);
    unpack2(accXAB, axA, axB); unpack2(accXCD, axC, axD);
    unpack2(accYAB, ayA, ayB); unpack2(accYCD, ayC, ayD);

    float4* P = g_part + (bh * SS) * NSPLIT;
    P[qi0 * NSPLIT + kc] = make_float4(mA, sA, axA, ayA);
    P[qi1 * NSPLIT + kc] = make_float4(mB, sB, axB, ayB);
    P[qi2 * NSPLIT + kc] = make_float4(mC, sC, axC, ayC);
    P[qi3 * NSPLIT + kc] = make_float4(mD, sD, axD, ayD);
}

// ---------------------------------------------------------------------------
// Kernel 3: combine attn partials; x += wo*o ; FFN ;
// then either LN1+QKV of next layer or final logits
// ---------------------------------------------------------------------------
__global__ void post_attn_kernel(const float* __restrict__ wo_l,
                                 const float* __restrict__ ln2_g_l,
                                 const float* __restrict__ ln2_b_l,
                                 const float* __restrict__ w1_l,
                                 const float* __restrict__ b1_l,
                                 const float* __restrict__ w2_l,
                                 const float* __restrict__ b2_l,
                                 const float* __restrict__ ln1_g_next,  // null if last
                                 const float* __restrict__ ln1_b_next,
                                 const float* __restrict__ wqkv_next,
                                 const float* __restrict__ out_w,       // used if last
                                 float* __restrict__ out,
                                 int last) {
    int t = blockIdx.x * blockDim.x + threadIdx.x;
    if (t >= NT) return;
    int b = t >> 10;
    int s = t & (SS - 1);

    // combine split-K softmax partials for both heads
    float o[EE];
#pragma unroll
    for (int h = 0; h < HH; h++) {
        const float4* P = g_part + ((b * HH + h) * SS + s) * NSPLIT;
        float4 p[NSPLIT];
#pragma unroll
        for (int c = 0; c < NSPLIT; c++) p[c] = P[c];
        float mm = p[0].x;
#pragma unroll
        for (int c = 1; c < NSPLIT; c++) mm = fmaxf(mm, p[c].x);
        float S = 0.f, ox = 0.f, oy = 0.f;
#pragma unroll
        for (int c = 0; c < NSPLIT; c++) {
            float sc = ex2f(p[c].x - mm);
            S  = fmaf(p[c].y, sc, S);
            ox = fmaf(p[c].z, sc, ox);
            oy = fmaf(p[c].w, sc, oy);
        }
        float r = __frcp_rn(S);
        o[h * 2 + 0] = ox * r;
        o[h * 2 + 1] = oy * r;
    }

    float4 x = g_x[t];
    float xv[EE] = {x.x, x.y, x.z, x.w};
    // x += wo @ o
#pragma unroll
    for (int f = 0; f < EE; f++) {
        const float* w = wo_l + f * EE;
        xv[f] += o[0] * __ldg(w) + o[1] * __ldg(w + 1) +
                 o[2] * __ldg(w + 2) + o[3] * __ldg(w + 3);
    }
    float4 xr = make_float4(xv[0], xv[1], xv[2], xv[3]);

    // FFN: x += w2 @ gelu(w1 @ LN2(x) + b1) + b2
    float h2[EE];
    layernorm4(xr, ln2_g_l, ln2_b_l, h2);
    float f1[FF];
#pragma unroll
    for (int f = 0; f < FF; f++) {
        const float* w = w1_l + f * EE;
        float acc = __ldg(b1_l + f) + h2[0] * __ldg(w) + h2[1] * __ldg(w + 1) +
                    h2[2] * __ldg(w + 2) + h2[3] * __ldg(w + 3);
        f1[f] = gelu_exact(acc);
    }
#pragma unroll
    for (int e = 0; e < EE; e++) {
        const float* w = w2_l + e * FF;
        float acc = __ldg(b2_l + e);
#pragma unroll
        for (int f = 0; f < FF; f++) acc = fmaf(f1[f], __ldg(w + f), acc);
        xv[e] += acc;
    }
    xr = make_float4(xv[0], xv[1], xv[2], xv[3]);
    g_x[t] = xr;

    if (last) {
#pragma unroll
        for (int v = 0; v < VV; v++) {
            const float* w = out_w + v * EE;
            out[t * VV + v] = xv[0] * __ldg(w) + xv[1] * __ldg(w + 1) +
                              xv[2] * __ldg(w + 2) + xv[3] * __ldg(w + 3);
        }
    } else {
        float hn[EE];
        layernorm4(xr, ln1_g_next, ln1_b_next, hn);
        qkv_project(t, hn, wqkv_next);
    }
}

// ---------------------------------------------------------------------------
// launch
// ---------------------------------------------------------------------------
extern "C" void kernel_launch(void* const* d_in, const int* in_sizes, int n_in,
                              void* d_out, int out_size) {
    const int*   token_ids = (const int*)d_in[0];
    const float* emb   = (const float*)d_in[1];
    const float* ln1_g = (const float*)d_in[2];
    const float* ln1_b = (const float*)d_in[3];
    const float* wqkv  = (const float*)d_in[4];
    const float* wo    = (const float*)d_in[5];
    const float* ln2_g = (const float*)d_in[6];
    const float* ln2_b = (const float*)d_in[7];
    const float* w1    = (const float*)d_in[8];
    const float* b1    = (const float*)d_in[9];
    const float* w2    = (const float*)d_in[10];
    const float* b2    = (const float*)d_in[11];
    const float* out_w = (const float*)d_in[12];
    float* out = (float*)d_out;

    const int TPB = 256;
    const int TOK_BLOCKS = NT / TPB;                 // 128
    const int ATTN_BLOCKS = BHN * 2 * NSPLIT;        // 1024
    const int ATTN_TPB = 128;

    // Layer 0
    embed_qkv_kernel<<<TOK_BLOCKS, TPB>>>(token_ids, emb, ln1_g, ln1_b, wqkv);
    attn_kernel<<<ATTN_BLOCKS, ATTN_TPB>>>();
    post_attn_kernel<<<TOK_BLOCKS, TPB>>>(
        wo + 0 * EE * EE, ln2_g + 0 * EE, ln2_b + 0 * EE,
        w1 + 0 * FF * EE, b1 + 0 * FF, w2 + 0 * EE * FF, b2 + 0 * EE,
        ln1_g + 1 * EE, ln1_b + 1 * EE, wqkv + 1 * 3 * EE * EE,
        out_w, out, /*last=*/0);

    // Layer 1
    attn_kernel<<<ATTN_BLOCKS, ATTN_TPB>>>();
    post_attn_kernel<<<TOK_BLOCKS, TPB>>>(
        wo + 1 * EE * EE, ln2_g + 1 * EE, ln2_b + 1 * EE,
        w1 + 1 * FF * EE, b1 + 1 * FF, w2 + 1 * EE * FF, b2 + 1 * EE,
        nullptr, nullptr, nullptr,
        out_w, out, /*last=*/1);
}

// round 12
// speedup vs baseline: 1.1128x; 1.1128x over previous
#include <cuda_runtime.h>
#include <math.h>

// Problem constants
#define BB   32
#define SS   1024
#define HH   2
#define EE   4
#define FF   16
#define VV   8
#define NT   (BB * SS)      // 32768 tokens
#define BHN  (BB * HH)      // 64 (b,h) pairs
#define NSPLIT 8
#define KCH  (SS / NSPLIT)  // 128 keys per block

typedef unsigned long long u64;

// Scratch (no runtime allocation allowed)
__device__ float4 g_x[NT];                 // residual stream [token][E]
__device__ float2 g_q[BHN * SS];           // per-(b,h) q, pre-scaled
__device__ float2 g_k[BHN * SS];
__device__ float2 g_v[BHN * SS];
__device__ float4 g_part[BHN * SS * NSPLIT]; // (sum, ox, oy, -) partials

// ---------------------------------------------------------------------------
// f32x2 packed-math helpers (sm_103a)
// ---------------------------------------------------------------------------
__device__ __forceinline__ u64 pack2(float lo, float hi) {
    u64 r;
    asm("mov.b64 %0, {%1, %2};" : "=l"(r)
        : "r"(__float_as_uint(lo)), "r"(__float_as_uint(hi)));
    return r;
}
__device__ __forceinline__ void unpack2(u64 v, float& lo, float& hi) {
    unsigned a, b;
    asm("mov.b64 {%0, %1}, %2;" : "=r"(a), "=r"(b) : "l"(v));
    lo = __uint_as_float(a);
    hi = __uint_as_float(b);
}
#define FMA2(d, a, b, c) \
    asm("fma.rn.f32x2 %0, %1, %2, %3;" : "=l"(d) : "l"(a), "l"(b), "l"(c))
#define MUL2(d, a, b) \
    asm("mul.rn.f32x2 %0, %1, %2;" : "=l"(d) : "l"(a), "l"(b))
#define ADD2(d, a, b) \
    asm("add.rn.f32x2 %0, %1, %2;" : "=l"(d) : "l"(a), "l"(b))

__device__ __forceinline__ float ex2f(float x) {
    float r;
    asm("ex2.approx.f32 %0, %1;" : "=f"(r) : "f"(x));
    return r;
}

// ---------------------------------------------------------------------------
// scalar helpers
// ---------------------------------------------------------------------------
__device__ __forceinline__ void layernorm4(float4 x, const float* __restrict__ g,
                                           const float* __restrict__ b, float* h) {
    float mu = 0.25f * (x.x + x.y + x.z + x.w);
    float d0 = x.x - mu, d1 = x.y - mu, d2 = x.z - mu, d3 = x.w - mu;
    float var = 0.25f * (d0 * d0 + d1 * d1 + d2 * d2 + d3 * d3);
    float r = rsqrtf(var + 1e-5f);
    h[0] = d0 * r * __ldg(g + 0) + __ldg(b + 0);
    h[1] = d1 * r * __ldg(g + 1) + __ldg(b + 1);
    h[2] = d2 * r * __ldg(g + 2) + __ldg(b + 2);
    h[3] = d3 * r * __ldg(g + 3) + __ldg(b + 3);
}

// qkv projection for one token, write q/k/v in (b,h,s,d) float2 layout
__device__ __forceinline__ void qkv_project(int t, const float* h,
                                            const float* __restrict__ wqkv_l) {
    float acc[12];
#pragma unroll
    for (int f = 0; f < 12; f++) {
        const float* w = wqkv_l + f * EE;
        acc[f] = h[0] * __ldg(w) + h[1] * __ldg(w + 1) +
                 h[2] * __ldg(w + 2) + h[3] * __ldg(w + 3);
    }
    int b = t >> 10;            // t / S
    int s = t & (SS - 1);
    // fold 1/sqrt(D) * log2(e) into q so attn does exp2 with no extra mul.
    // No softmax shift needed: LN-bounded inputs keep |score| < ~35 in exp2
    // units; exp2(35)*1024 ~ 3.5e13 << fp32 max, exp2(-35) >> denormal range.
    const float qs = 0.70710678118654752f * 1.4426950408889634f;
    g_q[(b * HH + 0) * SS + s] = make_float2(acc[0] * qs, acc[1] * qs);
    g_q[(b * HH + 1) * SS + s] = make_float2(acc[2] * qs, acc[3] * qs);
    g_k[(b * HH + 0) * SS + s] = make_float2(acc[4], acc[5]);
    g_k[(b * HH + 1) * SS + s] = make_float2(acc[6], acc[7]);
    g_v[(b * HH + 0) * SS + s] = make_float2(acc[8], acc[9]);
    g_v[(b * HH + 1) * SS + s] = make_float2(acc[10], acc[11]);
}

__device__ __forceinline__ float gelu_exact(float x) {
    return 0.5f * x * (1.0f + erff(x * 0.70710678118654752f));
}

// ---------------------------------------------------------------------------
// Kernel 1: embedding + LN1 + QKV (layer 0)
// ---------------------------------------------------------------------------
__global__ void embed_qkv_kernel(const int* __restrict__ token_ids,
                                 const float* __restrict__ emb,
                                 const float* __restrict__ ln1_g,
                                 const float* __restrict__ ln1_b,
                                 const float* __restrict__ wqkv) {
    int t = blockIdx.x * blockDim.x + threadIdx.x;
    if (t >= NT) return;
    int tok = __ldg(token_ids + t);
    const float* e = emb + tok * EE;
    float4 x = make_float4(__ldg(e), __ldg(e + 1), __ldg(e + 2), __ldg(e + 3));
    g_x[t] = x;
    float h[EE];
    layernorm4(x, ln1_g, ln1_b, h);
    qkv_project(t, h, wqkv);
}

// ---------------------------------------------------------------------------
// Kernel 2: attention partials, split-K over NSPLIT=8 chunks.
// 2 queries/thread, unshifted exp2 (see qkv_project note), KBATCH=4 load
// batching for smem MLP. Partials are plain (sum, ox, oy) -- combine is
// a simple add, no rescale.
// grid = 64 bh * 4 qchunks * 8 ksplits = 2048 blocks, 128 threads.
// ---------------------------------------------------------------------------
#define KBATCH 4
__global__ void __launch_bounds__(128, 8) attn_kernel() {
    __shared__ ulonglong2 sK[KCH];   // {kx,kx},{ky,ky}
    __shared__ ulonglong2 sV[KCH];   // {vx,vx},{vy,vy}

    int bx = blockIdx.x;
    int bh    = bx >> 5;
    int qc    = (bx >> 3) & 3;
    int kc    = bx & 7;
    int qbase = qc * 256;
    int kbase = kc * KCH;

    const float2* __restrict__ Kg = g_k + bh * SS + kbase;
    const float2* __restrict__ Vg = g_v + bh * SS + kbase;
    {
        int i = threadIdx.x;            // KCH == blockDim.x == 128
        float2 kk = Kg[i];
        float2 vv = Vg[i];
        sK[i] = make_ulonglong2(pack2(kk.x, kk.x), pack2(kk.y, kk.y));
        sV[i] = make_ulonglong2(pack2(vv.x, vv.x), pack2(vv.y, vv.y));
    }
    __syncthreads();

    int qi0 = qbase + threadIdx.x;
    int qi1 = qi0 + 128;
    const float2* __restrict__ Qg = g_q + bh * SS;
    float2 qa = Qg[qi0];   // pre-scaled by log2e/sqrt(D)
    float2 qb = Qg[qi1];

    u64 qx2 = pack2(qa.x, qb.x);
    u64 qy2 = pack2(qa.y, qb.y);

    u64 sum2 = pack2(0.f, 0.f);   // {sumA, sumB}
    u64 accX = sum2;              // {oxA, oxB}
    u64 accY = sum2;              // {oyA, oyB}

#pragma unroll 2
    for (int j0 = 0; j0 < KCH; j0 += KBATCH) {
        ulonglong2 kk[KBATCH], vv[KBATCH];
#pragma unroll
        for (int u = 0; u < KBATCH; u++) {
            kk[u] = sK[j0 + u];
            vv[u] = sV[j0 + u];
        }
        u64 arg[KBATCH];
#pragma unroll
        for (int u = 0; u < KBATCH; u++) {
            MUL2(arg[u], qy2, kk[u].y);
            FMA2(arg[u], qx2, kk[u].x, arg[u]);
        }
        float p0[KBATCH], p1[KBATCH];
#pragma unroll
        for (int u = 0; u < KBATCH; u++) {
            float a0, a1;
            unpack2(arg[u], a0, a1);
            p0[u] = ex2f(a0);
            p1[u] = ex2f(a1);
        }
#pragma unroll
        for (int u = 0; u < KBATCH; u++) {
            u64 p2 = pack2(p0[u], p1[u]);
            ADD2(sum2, sum2, p2);
            FMA2(accX, p2, vv[u].x, accX);
            FMA2(accY, p2, vv[u].y, accY);
        }
    }

    float sA, sB, axA, axB, ayA, ayB;
    unpack2(sum2, sA, sB);
    unpack2(accX, axA, axB);
    unpack2(accY, ayA, ayB);
    float4* P = g_part + (bh * SS) * NSPLIT;
    P[qi0 * NSPLIT + kc] = make_float4(sA, axA, ayA, 0.f);
    P[qi1 * NSPLIT + kc] = make_float4(sB, axB, ayB, 0.f);
}

// ---------------------------------------------------------------------------
// Kernel 3: combine attn partials (simple sums); x += wo*o ; FFN ;
// then either LN1+QKV of next layer or final logits
// ---------------------------------------------------------------------------
__global__ void post_attn_kernel(const float* __restrict__ wo_l,
                                 const float* __restrict__ ln2_g_l,
                                 const float* __restrict__ ln2_b_l,
                                 const float* __restrict__ w1_l,
                                 const float* __restrict__ b1_l,
                                 const float* __restrict__ w2_l,
                                 const float* __restrict__ b2_l,
                                 const float* __restrict__ ln1_g_next,  // null if last
                                 const float* __restrict__ ln1_b_next,
                                 const float* __restrict__ wqkv_next,
                                 const float* __restrict__ out_w,       // used if last
                                 float* __restrict__ out,
                                 int last) {
    int t = blockIdx.x * blockDim.x + threadIdx.x;
    if (t >= NT) return;
    int b = t >> 10;
    int s = t & (SS - 1);

    // combine split-K softmax partials for both heads (no shift: plain sums)
    float o[EE];
#pragma unroll
    for (int h = 0; h < HH; h++) {
        const float4* P = g_part + ((b * HH + h) * SS + s) * NSPLIT;
        float S = 0.f, ox = 0.f, oy = 0.f;
#pragma unroll
        for (int c = 0; c < NSPLIT; c++) {
            float4 p = P[c];
            S  += p.x;
            ox += p.y;
            oy += p.z;
        }
        float r = __frcp_rn(S);
        o[h * 2 + 0] = ox * r;
        o[h * 2 + 1] = oy * r;
    }

    float4 x = g_x[t];
    float xv[EE] = {x.x, x.y, x.z, x.w};
    // x += wo @ o
#pragma unroll
    for (int f = 0; f < EE; f++) {
        const float* w = wo_l + f * EE;
        xv[f] += o[0] * __ldg(w) + o[1] * __ldg(w + 1) +
                 o[2] * __ldg(w + 2) + o[3] * __ldg(w + 3);
    }
    float4 xr = make_float4(xv[0], xv[1], xv[2], xv[3]);

    // FFN: x += w2 @ gelu(w1 @ LN2(x) + b1) + b2
    float h2[EE];
    layernorm4(xr, ln2_g_l, ln2_b_l, h2);
    float f1[FF];
#pragma unroll
    for (int f = 0; f < FF; f++) {
        const float* w = w1_l + f * EE;
        float acc = __ldg(b1_l + f) + h2[0] * __ldg(w) + h2[1] * __ldg(w + 1) +
                    h2[2] * __ldg(w + 2) + h2[3] * __ldg(w + 3);
        f1[f] = gelu_exact(acc);
    }
#pragma unroll
    for (int e = 0; e < EE; e++) {
        const float* w = w2_l + e * FF;
        float acc = __ldg(b2_l + e);
#pragma unroll
        for (int f = 0; f < FF; f++) acc = fmaf(f1[f], __ldg(w + f), acc);
        xv[e] += acc;
    }
    xr = make_float4(xv[0], xv[1], xv[2], xv[3]);
    g_x[t] = xr;

    if (last) {
#pragma unroll
        for (int v = 0; v < VV; v++) {
            const float* w = out_w + v * EE;
            out[t * VV + v] = xv[0] * __ldg(w) + xv[1] * __ldg(w + 1) +
                              xv[2] * __ldg(w + 2) + xv[3] * __ldg(w + 3);
        }
    } else {
        float hn[EE];
        layernorm4(xr, ln1_g_next, ln1_b_next, hn);
        qkv_project(t, hn, wqkv_next);
    }
}

// ---------------------------------------------------------------------------
// launch
// ---------------------------------------------------------------------------
extern "C" void kernel_launch(void* const* d_in, const int* in_sizes, int n_in,
                              void* d_out, int out_size) {
    const int*   token_ids = (const int*)d_in[0];
    const float* emb   = (const float*)d_in[1];
    const float* ln1_g = (const float*)d_in[2];
    const float* ln1_b = (const float*)d_in[3];
    const float* wqkv  = (const float*)d_in[4];
    const float* wo    = (const float*)d_in[5];
    const float* ln2_g = (const float*)d_in[6];
    const float* ln2_b = (const float*)d_in[7];
    const float* w1    = (const float*)d_in[8];
    const float* b1    = (const float*)d_in[9];
    const float* w2    = (const float*)d_in[10];
    const float* b2    = (const float*)d_in[11];
    const float* out_w = (const float*)d_in[12];
    float* out = (float*)d_out;

    const int TPB = 128;                             // cover all 148 SMs
    const int TOK_BLOCKS = NT / TPB;                 // 256
    const int ATTN_BLOCKS = BHN * 4 * NSPLIT;        // 2048
    const int ATTN_TPB = 128;

    // Layer 0
    embed_qkv_kernel<<<TOK_BLOCKS, TPB>>>(token_ids, emb, ln1_g, ln1_b, wqkv);
    attn_kernel<<<ATTN_BLOCKS, ATTN_TPB>>>();
    post_attn_kernel<<<TOK_BLOCKS, TPB>>>(
        wo + 0 * EE * EE, ln2_g + 0 * EE, ln2_b + 0 * EE,
        w1 + 0 * FF * EE, b1 + 0 * FF, w2 + 0 * EE * FF, b2 + 0 * EE,
        ln1_g + 1 * EE, ln1_b + 1 * EE, wqkv + 1 * 3 * EE * EE,
        out_w, out, /*last=*/0);

    // Layer 1
    attn_kernel<<<ATTN_BLOCKS, ATTN_TPB>>>();
    post_attn_kernel<<<TOK_BLOCKS, TPB>>>(
        wo + 1 * EE * EE, ln2_g + 1 * EE, ln2_b + 1 * EE,
        w1 + 1 * FF * EE, b1 + 1 * FF, w2 + 1 * EE * FF, b2 + 1 * EE,
        nullptr, nullptr, nullptr,
        out_w, out, /*last=*/1);
}

// round 13
// speedup vs baseline: 4.1308x; 3.7121x over previous
#include <cuda_runtime.h>
#include <math.h>

// Problem constants
#define BB   32
#define SS   1024
#define HH   2
#define EE   4
#define FF   16
#define VV   8
#define NT   (BB * SS)      // 32768 tokens

// Key structural facts exploited:
//  - No positional encoding: attention output for position s depends only on
//    (batch, token_class(s)) and the per-batch class histogram.
//  - V=8: at most 8 distinct residual-stream values per batch at every depth.
// So the whole network runs on 32x8 "class tokens"; positions only enter via
// the histogram (exact regrouping: sum_j exp(q.k_cj) = sum_c count_c exp(q.k_c)).

__device__ int    g_cnt[BB * VV];          // per-batch class histogram
__device__ float4 g_logits[BB * VV * 2];   // [b][class][8 vocab] as 2x float4

__device__ __forceinline__ float ex2f(float x) {
    float r;
    asm("ex2.approx.f32 %0, %1;" : "=f"(r) : "f"(x));
    return r;
}

__device__ __forceinline__ void layernorm4(const float* x, const float* __restrict__ g,
                                           const float* __restrict__ b, float* h) {
    float mu = 0.25f * (x[0] + x[1] + x[2] + x[3]);
    float d0 = x[0] - mu, d1 = x[1] - mu, d2 = x[2] - mu, d3 = x[3] - mu;
    float var = 0.25f * (d0 * d0 + d1 * d1 + d2 * d2 + d3 * d3);
    float r = rsqrtf(var + 1e-5f);
    h[0] = d0 * r * __ldg(g + 0) + __ldg(b + 0);
    h[1] = d1 * r * __ldg(g + 1) + __ldg(b + 1);
    h[2] = d2 * r * __ldg(g + 2) + __ldg(b + 2);
    h[3] = d3 * r * __ldg(g + 3) + __ldg(b + 3);
}

__device__ __forceinline__ float gelu_exact(float x) {
    return 0.5f * x * (1.0f + erff(x * 0.70710678118654752f));
}

// ---------------------------------------------------------------------------
// Kernel 1: per-batch class histogram. grid = 32 blocks, 256 threads.
// ---------------------------------------------------------------------------
__global__ void hist_kernel(const int* __restrict__ token_ids) {
    __shared__ int cnt[VV];
    int b = blockIdx.x;
    if (threadIdx.x < VV) cnt[threadIdx.x] = 0;
    __syncthreads();
    const int4* T = (const int4*)(token_ids + b * SS);
#pragma unroll
    for (int i = 0; i < SS / 4 / 256; i++) {   // 1 int4 per thread
        int4 tt = T[i * 256 + threadIdx.x];
        atomicAdd(&cnt[tt.x], 1);
        atomicAdd(&cnt[tt.y], 1);
        atomicAdd(&cnt[tt.z], 1);
        atomicAdd(&cnt[tt.w], 1);
    }
    __syncthreads();
    if (threadIdx.x < VV) g_cnt[b * VV + threadIdx.x] = cnt[threadIdx.x];
}

// ---------------------------------------------------------------------------
// Kernel 2: class network. ONE block, 256 threads = one per (batch, class).
// Full 2-layer transformer forward on class tokens; attention over 8 classes
// weighted by histogram counts (exact regrouping of the reference softmax).
// ---------------------------------------------------------------------------
__global__ void __launch_bounds__(BB * VV) classnet_kernel(
        const float* __restrict__ emb,
        const float* __restrict__ ln1_g, const float* __restrict__ ln1_b,
        const float* __restrict__ wqkv,  const float* __restrict__ wo,
        const float* __restrict__ ln2_g, const float* __restrict__ ln2_b,
        const float* __restrict__ w1,    const float* __restrict__ b1,
        const float* __restrict__ w2,    const float* __restrict__ b2,
        const float* __restrict__ out_w) {
    __shared__ float2 sk[HH][BB * VV];
    __shared__ float2 sv[HH][BB * VV];
    __shared__ float  scnt[BB * VV];

    int tid = threadIdx.x;
    int b   = tid >> 3;
    int c   = tid & 7;
    int base = b * VV;

    scnt[tid] = (float)g_cnt[tid];

    // x = emb[class]
    float x[EE];
#pragma unroll
    for (int e = 0; e < EE; e++) x[e] = __ldg(emb + c * EE + e);

    const float qs = 0.70710678118654752f * 1.4426950408889634f; // 1/sqrt(D)*log2e

#pragma unroll
    for (int l = 0; l < 2; l++) {
        // LN1 + qkv projection
        float h[EE];
        layernorm4(x, ln1_g + l * EE, ln1_b + l * EE, h);
        const float* wq = wqkv + l * 3 * EE * EE;
        float acc[12];
#pragma unroll
        for (int f = 0; f < 12; f++) {
            const float* w = wq + f * EE;
            acc[f] = h[0] * __ldg(w) + h[1] * __ldg(w + 1) +
                     h[2] * __ldg(w + 2) + h[3] * __ldg(w + 3);
        }
        float2 q0 = make_float2(acc[0] * qs, acc[1] * qs);
        float2 q1 = make_float2(acc[2] * qs, acc[3] * qs);
        sk[0][tid] = make_float2(acc[4], acc[5]);
        sk[1][tid] = make_float2(acc[6], acc[7]);
        sv[0][tid] = make_float2(acc[8], acc[9]);
        sv[1][tid] = make_float2(acc[10], acc[11]);
        __syncthreads();

        // attention over 8 classes, count-weighted (no shift needed: LN-bounded
        // scores keep exp2 args ~|35|, far from fp32 limits)
        float o[EE];
#pragma unroll
        for (int hh = 0; hh < HH; hh++) {
            float2 q = hh ? q1 : q0;
            float S = 0.f, ox = 0.f, oy = 0.f;
#pragma unroll
            for (int cc = 0; cc < VV; cc++) {
                float2 kk = sk[hh][base + cc];
                float2 vv = sv[hh][base + cc];
                float w = scnt[base + cc] * ex2f(fmaf(q.x, kk.x, q.y * kk.y));
                S  += w;
                ox = fmaf(w, vv.x, ox);
                oy = fmaf(w, vv.y, oy);
            }
            float r = __frcp_rn(S);
            o[hh * 2 + 0] = ox * r;
            o[hh * 2 + 1] = oy * r;
        }
        __syncthreads();   // reads done before next layer overwrites smem

        // x += wo @ o
        const float* wol = wo + l * EE * EE;
#pragma unroll
        for (int f = 0; f < EE; f++) {
            const float* w = wol + f * EE;
            x[f] += o[0] * __ldg(w) + o[1] * __ldg(w + 1) +
                    o[2] * __ldg(w + 2) + o[3] * __ldg(w + 3);
        }

        // FFN
        float h2[EE];
        layernorm4(x, ln2_g + l * EE, ln2_b + l * EE, h2);
        float f1[FF];
        const float* w1l = w1 + l * FF * EE;
#pragma unroll
        for (int f = 0; f < FF; f++) {
            const float* w = w1l + f * EE;
            float a = __ldg(b1 + l * FF + f) +
                      h2[0] * __ldg(w) + h2[1] * __ldg(w + 1) +
                      h2[2] * __ldg(w + 2) + h2[3] * __ldg(w + 3);
            f1[f] = gelu_exact(a);
        }
        const float* w2l = w2 + l * EE * FF;
#pragma unroll
        for (int e = 0; e < EE; e++) {
            const float* w = w2l + e * FF;
            float a = __ldg(b2 + l * EE + e);
#pragma unroll
            for (int f = 0; f < FF; f++) a = fmaf(f1[f], __ldg(w + f), a);
            x[e] += a;
        }
    }

    // logits for this (b, class): 8 dots of 4
    float lg[VV];
#pragma unroll
    for (int v = 0; v < VV; v++) {
        const float* w = out_w + v * EE;
        lg[v] = x[0] * __ldg(w) + x[1] * __ldg(w + 1) +
                x[2] * __ldg(w + 2) + x[3] * __ldg(w + 3);
    }
    g_logits[tid * 2 + 0] = make_float4(lg[0], lg[1], lg[2], lg[3]);
    g_logits[tid * 2 + 1] = make_float4(lg[4], lg[5], lg[6], lg[7]);
}

// ---------------------------------------------------------------------------
// Kernel 3: gather logits to every position. grid = 128 blocks x 256 thr.
// ---------------------------------------------------------------------------
__global__ void gather_kernel(const int* __restrict__ token_ids,
                              float4* __restrict__ out) {
    int t = blockIdx.x * blockDim.x + threadIdx.x;
    if (t >= NT) return;
    int b   = t >> 10;
    int tok = __ldg(token_ids + t);
    int idx = (b * VV + tok) * 2;
    float4 a = g_logits[idx];
    float4 c = g_logits[idx + 1];
    out[t * 2 + 0] = a;
    out[t * 2 + 1] = c;
}

// ---------------------------------------------------------------------------
// launch
// ---------------------------------------------------------------------------
extern "C" void kernel_launch(void* const* d_in, const int* in_sizes, int n_in,
                              void* d_out, int out_size) {
    const int*   token_ids = (const int*)d_in[0];
    const float* emb   = (const float*)d_in[1];
    const float* ln1_g = (const float*)d_in[2];
    const float* ln1_b = (const float*)d_in[3];
    const float* wqkv  = (const float*)d_in[4];
    const float* wo    = (const float*)d_in[5];
    const float* ln2_g = (const float*)d_in[6];
    const float* ln2_b = (const float*)d_in[7];
    const float* w1    = (const float*)d_in[8];
    const float* b1    = (const float*)d_in[9];
    const float* w2    = (const float*)d_in[10];
    const float* b2    = (const float*)d_in[11];
    const float* out_w = (const float*)d_in[12];
    float4* out = (float4*)d_out;

    hist_kernel<<<BB, 256>>>(token_ids);
    classnet_kernel<<<1, BB * VV>>>(emb, ln1_g, ln1_b, wqkv, wo,
                                    ln2_g, ln2_b, w1, b1, w2, b2, out_w);
    gather_kernel<<<NT / 256, 256>>>(token_ids, out);
}